// round 9
// baseline (speedup 1.0000x reference)
#include <cuda_runtime.h>

#define B_   4
#define C_   256
#define CR_  32
#define N_   4096
#define EPS_ 1e-5f
#define SEXP_ 0.25503486f   // (1/sqrt(32)) * log2(e)

// ---------------- scratch (device globals; no allocations) ----------------
__device__ float g_q [B_*CR_*N_];
__device__ float g_k [B_*CR_*N_];
__device__ float g_v [B_*C_*N_];
__device__ float g_ao[B_*C_*N_];
__device__ float g_y [B_*C_*N_];

// ---------------- helpers ----------------
__device__ __forceinline__ unsigned tf32r(float x){
    unsigned r; asm("cvt.rna.tf32.f32 %0, %1;" : "=r"(r) : "f"(x)); return r;
}
__device__ __forceinline__ float tf32f(float x){ return __uint_as_float(tf32r(x)); }
__device__ __forceinline__ float ex2(float x){
    float r; asm("ex2.approx.f32 %0, %1;" : "=f"(r) : "f"(x)); return r;
}
__device__ __forceinline__ void mma8(float* d, const unsigned* a, const unsigned* b){
    asm volatile("mma.sync.aligned.m16n8k8.row.col.f32.tf32.tf32.f32 "
        "{%0,%1,%2,%3},{%4,%5,%6,%7},{%8,%9},{%0,%1,%2,%3};"
        : "+f"(d[0]), "+f"(d[1]), "+f"(d[2]), "+f"(d[3])
        : "r"(a[0]), "r"(a[1]), "r"(a[2]), "r"(a[3]), "r"(b[0]), "r"(b[1]));
}
__device__ __forceinline__ void cp16(unsigned daddr, const void* src){
    asm volatile("cp.async.cg.shared.global [%0], [%1], 16;" :: "r"(daddr), "l"(src));
}
__device__ __forceinline__ void cpcommit(){ asm volatile("cp.async.commit_group;"); }
template<int n> __device__ __forceinline__ void cpwait(){
    asm volatile("cp.async.wait_group %0;" :: "n"(n));
}

// ============================================================================
// Channel GEMM body: Y[b,o(+o0),n] = sum_c W[o0+o,c] * X[b,c,n]   (K = 256)
// CTA: 64o x 128n, 256 threads (8 warps, 2m x 4n), K chunks of 32, X double-buf.
// ============================================================================
#define GWS 260
#define GXS 132
#define GXO (64*GWS)
#define GXBUF (32*GXS)
#define GEMM_SMEM ((GXO + 2*GXBUF)*4)

__device__ __forceinline__ void gemm_body(const float* __restrict__ W,
                                          const float* __restrict__ X,
                                          float* __restrict__ Y,
                                          int OC, int o0, int round_out)
{
    extern __shared__ float sm[];
    unsigned* smu = (unsigned*)sm;
    unsigned sbase = (unsigned)__cvta_generic_to_shared(sm);

    const int tid = threadIdx.x, lane = tid & 31, wid = tid >> 5;
    const int g = lane >> 2, t = lane & 3;
    const int mw = wid >> 2, nw = wid & 3;
    const int n0 = blockIdx.x * 128;
    const int b  = blockIdx.z;
    const float* Xb = X + (size_t)b * C_ * N_;

#pragma unroll
    for (int s = 0; s < 16; s++) {
        int u = tid + 256 * s;
        int o = u >> 6, c4 = (u & 63) * 4;
        float4 w4 = make_float4(0.f, 0.f, 0.f, 0.f);
        if (o0 + o < OC) w4 = *(const float4*)&W[(size_t)(o0 + o) * C_ + c4];
        w4.x = tf32f(w4.x); w4.y = tf32f(w4.y); w4.z = tf32f(w4.z); w4.w = tf32f(w4.w);
        *(float4*)&sm[o * GWS + c4] = w4;
    }

    auto loadX = [&](int kc, int bf) {
#pragma unroll
        for (int s = 0; s < 4; s++) {
            int u = tid + 256 * s;
            int c = u >> 5, n4 = (u & 31) * 4;
            cp16(sbase + (GXO + bf * GXBUF + c * GXS + n4) * 4,
                 &Xb[(size_t)(kc * 32 + c) * N_ + n0 + n4]);
        }
    };

    float acc[2][4][4];
#pragma unroll
    for (int i = 0; i < 2; i++)
#pragma unroll
        for (int j = 0; j < 4; j++)
#pragma unroll
            for (int e = 0; e < 4; e++) acc[i][j][e] = 0.f;

    loadX(0, 0); cpcommit();

    for (int kc = 0; kc < 8; kc++) {
        int bf = kc & 1;
        if (kc < 7) { loadX(kc + 1, bf ^ 1); cpcommit(); cpwait<1>(); }
        else        { cpwait<0>(); }
        __syncthreads();

        const int xb = GXO + bf * GXBUF;
        const int wcol = kc * 32;
#pragma unroll
        for (int k = 0; k < 4; k++) {
            int kk = 8 * k;
            unsigned a[2][4];
#pragma unroll
            for (int mt = 0; mt < 2; mt++) {
                int orow = 32 * mw + 16 * mt;
                a[mt][0] = smu[(orow + g)     * GWS + wcol + kk + t];
                a[mt][1] = smu[(orow + g + 8) * GWS + wcol + kk + t];
                a[mt][2] = smu[(orow + g)     * GWS + wcol + kk + t + 4];
                a[mt][3] = smu[(orow + g + 8) * GWS + wcol + kk + t + 4];
            }
#pragma unroll
            for (int nt = 0; nt < 4; nt++) {
                int nn = 32 * nw + 8 * nt;
                unsigned bb[2];
                bb[0] = smu[xb + (kk + t)     * GXS + nn + g];
                bb[1] = smu[xb + (kk + t + 4) * GXS + nn + g];
                mma8(acc[0][nt], a[0], bb);
                mma8(acc[1][nt], a[1], bb);
            }
        }
        __syncthreads();
    }

#pragma unroll
    for (int mt = 0; mt < 2; mt++) {
        int orow = o0 + 32 * mw + 16 * mt;
#pragma unroll
        for (int nt = 0; nt < 4; nt++) {
            int col = n0 + 32 * nw + 8 * nt + 2 * t;
            float e0 = acc[mt][nt][0], e1 = acc[mt][nt][1];
            float e2 = acc[mt][nt][2], e3 = acc[mt][nt][3];
            if (round_out) { e0 = tf32f(e0); e1 = tf32f(e1); e2 = tf32f(e2); e3 = tf32f(e3); }
            if (orow + g < OC)
                *(float2*)&Y[((size_t)b * OC + orow + g) * N_ + col] = make_float2(e0, e1);
            if (orow + g + 8 < OC)
                *(float2*)&Y[((size_t)b * OC + orow + g + 8) * N_ + col] = make_float2(e2, e3);
        }
    }
}

// fused q/k/v: blockIdx.y selects which GEMM
__global__ __launch_bounds__(256, 2) void gemm_qkv(const float* __restrict__ x1,
                                                   const float* __restrict__ x2,
                                                   const float* __restrict__ wq,
                                                   const float* __restrict__ wk,
                                                   const float* __restrict__ wv,
                                                   float* __restrict__ q,
                                                   float* __restrict__ k,
                                                   float* __restrict__ v)
{
    int y = blockIdx.y;
    if      (y == 0) gemm_body(wq, x1, q, CR_, 0, 1);
    else if (y == 1) gemm_body(wk, x2, k, CR_, 0, 1);
    else             gemm_body(wv, x2, v, C_, (y - 2) * 64, 1);
}

__global__ __launch_bounds__(256, 2) void gemm_proj(const float* __restrict__ wp,
                                                    const float* __restrict__ ao,
                                                    float* __restrict__ yo)
{
    gemm_body(wp, ao, yo, C_, blockIdx.y * 64, 0);
}

// ============================================================================
// Attention: CTA = 64q x 256c per batch, 256 threads / 8 warps, JT=32.
// 2 CTAs/SM (~102 KB smem, <=128 regs) so sibling CTAs overlap phases.
// S warp tile 16q x 16j; PV warp tile 32q x 64c (64 acc regs).
// ============================================================================
#define AQS 0                        // [64][36]
#define AKS 2304                     // 2 x [32][36]
#define AKB 1152
#define APS 4608                     // [64][36]
#define AVS 6912                     // 2 x [256][36]
#define AVB 9216
#define ALP 25344                    // [64][2]
#define ALS 25472                    // [64]
#define AOS 0                        // epilogue overlay [256][68] (Q/K/P dead by then)
#define ATTN_SMEM (25536*4)

__global__ __launch_bounds__(256, 2) void attn_mma()
{
    extern __shared__ float sm[];
    unsigned* smu = (unsigned*)sm;
    unsigned sbase = (unsigned)__cvta_generic_to_shared(sm);

    const int tid = threadIdx.x, lane = tid & 31, wid = tid >> 5;
    const int g = lane >> 2, t = lane & 3;
    const int q0 = blockIdx.x * 64;
    const int b  = blockIdx.y;
    // S roles: 4 q-blocks x 2 j-halves
    const int mq = wid & 3, nh = wid >> 2;
    const int qrow = 16 * mq;
    // PV roles: 2 q-halves x 4 c-blocks
    const int qw = wid & 1, cw = wid >> 1;

    // ---- prologue: transpose-load Q tile -> qs[q][c] ----
#pragma unroll
    for (int s = 0; s < 2; s++) {
        int u = tid + 256 * s;               // 512 units: 32c x 16(q/4)
        int c = u >> 4, q4 = (u & 15) * 4;
        float4 f = *(const float4*)&g_q[((size_t)b * CR_ + c) * N_ + q0 + q4];
        sm[AQS + (q4 + 0) * 36 + c] = f.x;
        sm[AQS + (q4 + 1) * 36 + c] = f.y;
        sm[AQS + (q4 + 2) * 36 + c] = f.z;
        sm[AQS + (q4 + 3) * 36 + c] = f.w;
    }

    auto loadKV = [&](int jt, int p) {
        int j0 = jt * 32;
        {   // K: 32c x 32j = 256 float4 units
            int c = tid >> 3, j4 = (tid & 7) * 4;
            cp16(sbase + (AKS + p * AKB + c * 36 + j4) * 4,
                 &g_k[((size_t)b * CR_ + c) * N_ + j0 + j4]);
        }
#pragma unroll
        for (int s = 0; s < 8; s++) {        // V: 256c x 32j = 2048 float4 units
            int u = tid + 256 * s;
            int c = u >> 3, j4 = (u & 7) * 4;
            cp16(sbase + (AVS + p * AVB + c * 36 + j4) * 4,
                 &g_v[((size_t)b * C_ + c) * N_ + j0 + j4]);
        }
    };

    float oacc[2][8][4];
#pragma unroll
    for (int i = 0; i < 2; i++)
#pragma unroll
        for (int j = 0; j < 8; j++)
#pragma unroll
            for (int e = 0; e < 4; e++) oacc[i][j][e] = 0.f;

    float lr0 = 0.f, lr1 = 0.f;              // denominators for rows qrow+g, qrow+g+8

    loadKV(0, 0); cpcommit();

    for (int jt = 0; jt < N_ / 32; jt++) {
        const int p = jt & 1;
        cpwait<0>();
        __syncthreads();   // KV(p) visible; S/PV of jt-1 done with p^1 and PS

        if (jt + 1 < N_ / 32) { loadKV(jt + 1, p ^ 1); cpcommit(); }

        // ---- S = Q^T K (16q x 16j per warp), p = exp2(S*SEXP) -> PS ----
        {
            const int kb = AKS + p * AKB;
            float sacc[2][4];
#pragma unroll
            for (int nt = 0; nt < 2; nt++)
#pragma unroll
                for (int e = 0; e < 4; e++) sacc[nt][e] = 0.f;
#pragma unroll
            for (int k = 0; k < 4; k++) {
                int kk = 8 * k;
                unsigned a[4];
                a[0] = smu[AQS + (qrow + g)     * 36 + kk + t];
                a[1] = smu[AQS + (qrow + g + 8) * 36 + kk + t];
                a[2] = smu[AQS + (qrow + g)     * 36 + kk + t + 4];
                a[3] = smu[AQS + (qrow + g + 8) * 36 + kk + t + 4];
#pragma unroll
                for (int nt = 0; nt < 2; nt++) {
                    int jj = 16 * nh + 8 * nt;
                    unsigned bb[2];
                    bb[0] = smu[kb + (kk + t)     * 36 + jj + g];
                    bb[1] = smu[kb + (kk + t + 4) * 36 + jj + g];
                    mma8(sacc[nt], a, bb);
                }
            }
            const int r0 = qrow + g, r1 = qrow + g + 8;
#pragma unroll
            for (int nt = 0; nt < 2; nt++) {
                int jj = 16 * nh + 8 * nt + 2 * t;
                float e0 = tf32f(ex2(sacc[nt][0] * SEXP_));
                float e1 = tf32f(ex2(sacc[nt][1] * SEXP_));
                float e2 = tf32f(ex2(sacc[nt][2] * SEXP_));
                float e3 = tf32f(ex2(sacc[nt][3] * SEXP_));
                lr0 += e0 + e1; lr1 += e2 + e3;
                *(float2*)&sm[APS + r0 * 36 + jj] = make_float2(e0, e1);
                *(float2*)&sm[APS + r1 * 36 + jj] = make_float2(e2, e3);
            }
        }
        __syncthreads();   // PS ready

        // ---- O += P V^T (32q x 64c per warp) ----
        {
            const int vb = AVS + p * AVB;
#pragma unroll
            for (int k = 0; k < 4; k++) {
                int kk = 8 * k;
                unsigned a[2][4];
#pragma unroll
                for (int mt = 0; mt < 2; mt++) {
                    int r = 32 * qw + 16 * mt;
                    a[mt][0] = smu[APS + (r + g)     * 36 + kk + t];
                    a[mt][1] = smu[APS + (r + g + 8) * 36 + kk + t];
                    a[mt][2] = smu[APS + (r + g)     * 36 + kk + t + 4];
                    a[mt][3] = smu[APS + (r + g + 8) * 36 + kk + t + 4];
                }
#pragma unroll
                for (int nt = 0; nt < 8; nt++) {
                    int cc = 64 * cw + 8 * nt;
                    unsigned bb[2];
                    bb[0] = smu[vb + (cc + g) * 36 + kk + t];
                    bb[1] = smu[vb + (cc + g) * 36 + kk + t + 4];
                    mma8(oacc[0][nt], a[0], bb);
                    mma8(oacc[1][nt], a[1], bb);
                }
            }
        }
        // next iteration's top barrier protects PS and V(p)
    }

    // ---- denominators ----
    lr0 += __shfl_xor_sync(0xffffffffu, lr0, 1); lr0 += __shfl_xor_sync(0xffffffffu, lr0, 2);
    lr1 += __shfl_xor_sync(0xffffffffu, lr1, 1); lr1 += __shfl_xor_sync(0xffffffffu, lr1, 2);
    if (t == 0) {
        sm[ALP + (qrow + g)     * 2 + nh] = lr0;
        sm[ALP + (qrow + g + 8) * 2 + nh] = lr1;
    }
    __syncthreads();                       // all PV done -> Q/K/P regions dead
    if (tid < 64) sm[ALS + tid] = 1.f / (sm[ALP + 2 * tid] + sm[ALP + 2 * tid + 1]);
    __syncthreads();

    // ---- scale + transpose through smem overlay, coalesced store ----
#pragma unroll
    for (int mt = 0; mt < 2; mt++) {
        int row0 = 32 * qw + 16 * mt + g;
        float inv0 = sm[ALS + row0];
        float inv1 = sm[ALS + row0 + 8];
#pragma unroll
        for (int nt = 0; nt < 8; nt++) {
            int cc = 64 * cw + 8 * nt + 2 * t;
            sm[AOS + cc       * 68 + row0]     = tf32f(oacc[mt][nt][0] * inv0);
            sm[AOS + (cc + 1) * 68 + row0]     = tf32f(oacc[mt][nt][1] * inv0);
            sm[AOS + cc       * 68 + row0 + 8] = tf32f(oacc[mt][nt][2] * inv1);
            sm[AOS + (cc + 1) * 68 + row0 + 8] = tf32f(oacc[mt][nt][3] * inv1);
        }
    }
    __syncthreads();
#pragma unroll
    for (int s = 0; s < 16; s++) {
        int u = tid + 256 * s;               // 4096 float4 units: 256c x 16(q/4)
        int c = u >> 4, q4 = (u & 15) * 4;
        float4 f = *(const float4*)&sm[AOS + c * 68 + q4];
        *(float4*)&g_ao[((size_t)b * C_ + c) * N_ + q0 + q4] = f;
    }
}

// ---------------- instance norm + residual ----------------
__global__ __launch_bounds__(256) void norm_kernel(const float* __restrict__ x1,
                                                   float* __restrict__ out)
{
    int row = blockIdx.x;
    const float* yr = g_y + (size_t)row * N_;
    const float* xr = x1  + (size_t)row * N_;
    float*       orow = out + (size_t)row * N_;
    int tid = threadIdx.x;

    float4 v[4];
    float s = 0.f, ss = 0.f;
#pragma unroll
    for (int k = 0; k < 4; k++) {
        v[k] = *(const float4*)&yr[(tid + 256 * k) * 4];
        s  += v[k].x + v[k].y + v[k].z + v[k].w;
        ss += v[k].x * v[k].x + v[k].y * v[k].y + v[k].z * v[k].z + v[k].w * v[k].w;
    }
#pragma unroll
    for (int o = 16; o; o >>= 1) {
        s  += __shfl_xor_sync(0xffffffffu, s,  o);
        ss += __shfl_xor_sync(0xffffffffu, ss, o);
    }
    __shared__ float rs[8], rss[8];
    __shared__ float stats[2];
    if ((tid & 31) == 0) { rs[tid >> 5] = s; rss[tid >> 5] = ss; }
    __syncthreads();
    if (tid < 32) {
        float a  = (tid < 8) ? rs[tid]  : 0.f;
        float b2 = (tid < 8) ? rss[tid] : 0.f;
#pragma unroll
        for (int o = 4; o; o >>= 1) {
            a  += __shfl_xor_sync(0xffffffffu, a,  o);
            b2 += __shfl_xor_sync(0xffffffffu, b2, o);
        }
        if (tid == 0) {
            float mean = a * (1.f / N_);
            float var  = b2 * (1.f / N_) - mean * mean;
            stats[0] = mean;
            stats[1] = rsqrtf(var + EPS_);
        }
    }
    __syncthreads();
    float mean = stats[0], inv = stats[1];
#pragma unroll
    for (int k = 0; k < 4; k++) {
        float4 x4 = *(const float4*)&xr[(tid + 256 * k) * 4];
        float4 o4;
        o4.x = (v[k].x - mean) * inv + x4.x;
        o4.y = (v[k].y - mean) * inv + x4.y;
        o4.z = (v[k].z - mean) * inv + x4.z;
        o4.w = (v[k].w - mean) * inv + x4.w;
        *(float4*)&orow[(tid + 256 * k) * 4] = o4;
    }
}

// ---------------- launcher ----------------
extern "C" void kernel_launch(void* const* d_in, const int* in_sizes, int n_in,
                              void* d_out, int out_size)
{
    (void)in_sizes; (void)n_in; (void)out_size;
    const float* x1 = (const float*)d_in[0];
    const float* x2 = (const float*)d_in[1];
    const float* wq = (const float*)d_in[2];
    const float* wk = (const float*)d_in[3];
    const float* wv = (const float*)d_in[4];
    const float* wp = (const float*)d_in[5];
    float* out = (float*)d_out;

    void *qp, *kp, *vp, *aop, *yp;
    cudaGetSymbolAddress(&qp,  g_q);
    cudaGetSymbolAddress(&kp,  g_k);
    cudaGetSymbolAddress(&vp,  g_v);
    cudaGetSymbolAddress(&aop, g_ao);
    cudaGetSymbolAddress(&yp,  g_y);

    cudaFuncSetAttribute(gemm_qkv,  cudaFuncAttributeMaxDynamicSharedMemorySize, GEMM_SMEM);
    cudaFuncSetAttribute(gemm_proj, cudaFuncAttributeMaxDynamicSharedMemorySize, GEMM_SMEM);
    cudaFuncSetAttribute(attn_mma,  cudaFuncAttributeMaxDynamicSharedMemorySize, ATTN_SMEM);

    gemm_qkv<<<dim3(N_/128, 6, B_), 256, GEMM_SMEM>>>(x1, x2, wq, wk, wv,
                                                      (float*)qp, (float*)kp, (float*)vp);
    attn_mma<<<dim3(N_/64, B_), 256, ATTN_SMEM>>>();
    gemm_proj<<<dim3(N_/128, C_/64, B_), 256, GEMM_SMEM>>>(wp, (const float*)aop, (float*)yp);
    norm_kernel<<<B_*C_, 256>>>(x1, out);
}

// round 10
// speedup vs baseline: 1.2186x; 1.2186x over previous
#include <cuda_runtime.h>

#define B_   4
#define C_   256
#define CR_  32
#define N_   4096
#define EPS_ 1e-5f
#define SEXP_ 0.25503486f   // (1/sqrt(32)) * log2(e)

// ---------------- scratch (device globals; no allocations) ----------------
__device__ float g_q [B_*CR_*N_];
__device__ float g_k [B_*CR_*N_];
__device__ float g_v [B_*C_*N_];
__device__ float g_ao[B_*C_*N_];
__device__ float g_y [B_*C_*N_];

// ---------------- helpers ----------------
__device__ __forceinline__ unsigned tf32r(float x){
    unsigned r; asm("cvt.rna.tf32.f32 %0, %1;" : "=r"(r) : "f"(x)); return r;
}
__device__ __forceinline__ float tf32f(float x){ return __uint_as_float(tf32r(x)); }
__device__ __forceinline__ float ex2(float x){
    float r; asm("ex2.approx.f32 %0, %1;" : "=f"(r) : "f"(x)); return r;
}
__device__ __forceinline__ void mma8(float* d, const unsigned* a, const unsigned* b){
    asm volatile("mma.sync.aligned.m16n8k8.row.col.f32.tf32.tf32.f32 "
        "{%0,%1,%2,%3},{%4,%5,%6,%7},{%8,%9},{%0,%1,%2,%3};"
        : "+f"(d[0]), "+f"(d[1]), "+f"(d[2]), "+f"(d[3])
        : "r"(a[0]), "r"(a[1]), "r"(a[2]), "r"(a[3]), "r"(b[0]), "r"(b[1]));
}
__device__ __forceinline__ void cp16(unsigned daddr, const void* src){
    asm volatile("cp.async.cg.shared.global [%0], [%1], 16;" :: "r"(daddr), "l"(src));
}
__device__ __forceinline__ void cpcommit(){ asm volatile("cp.async.commit_group;"); }
template<int n> __device__ __forceinline__ void cpwait(){
    asm volatile("cp.async.wait_group %0;" :: "n"(n));
}

// ============================================================================
// Channel GEMM body: Y[b,o(+o0),n] = sum_c W[o0+o,c] * X[b,c,n]   (K = 256)
// CTA: 64o x 128n, 256 threads (8 warps, 2m x 4n), K chunks of 32, X double-buf.
// ============================================================================
#define GWS 260
#define GXS 132
#define GXO (64*GWS)
#define GXBUF (32*GXS)
#define GEMM_SMEM ((GXO + 2*GXBUF)*4)

__device__ __forceinline__ void gemm_body(const float* __restrict__ W,
                                          const float* __restrict__ X,
                                          float* __restrict__ Y,
                                          int OC, int o0, int round_out)
{
    extern __shared__ float sm[];
    unsigned* smu = (unsigned*)sm;
    unsigned sbase = (unsigned)__cvta_generic_to_shared(sm);

    const int tid = threadIdx.x, lane = tid & 31, wid = tid >> 5;
    const int g = lane >> 2, t = lane & 3;
    const int mw = wid >> 2, nw = wid & 3;
    const int n0 = blockIdx.x * 128;
    const int b  = blockIdx.z;
    const float* Xb = X + (size_t)b * C_ * N_;

#pragma unroll
    for (int s = 0; s < 16; s++) {
        int u = tid + 256 * s;
        int o = u >> 6, c4 = (u & 63) * 4;
        float4 w4 = make_float4(0.f, 0.f, 0.f, 0.f);
        if (o0 + o < OC) w4 = *(const float4*)&W[(size_t)(o0 + o) * C_ + c4];
        w4.x = tf32f(w4.x); w4.y = tf32f(w4.y); w4.z = tf32f(w4.z); w4.w = tf32f(w4.w);
        *(float4*)&sm[o * GWS + c4] = w4;
    }

    auto loadX = [&](int kc, int bf) {
#pragma unroll
        for (int s = 0; s < 4; s++) {
            int u = tid + 256 * s;
            int c = u >> 5, n4 = (u & 31) * 4;
            cp16(sbase + (GXO + bf * GXBUF + c * GXS + n4) * 4,
                 &Xb[(size_t)(kc * 32 + c) * N_ + n0 + n4]);
        }
    };

    float acc[2][4][4];
#pragma unroll
    for (int i = 0; i < 2; i++)
#pragma unroll
        for (int j = 0; j < 4; j++)
#pragma unroll
            for (int e = 0; e < 4; e++) acc[i][j][e] = 0.f;

    loadX(0, 0); cpcommit();

    for (int kc = 0; kc < 8; kc++) {
        int bf = kc & 1;
        if (kc < 7) { loadX(kc + 1, bf ^ 1); cpcommit(); cpwait<1>(); }
        else        { cpwait<0>(); }
        __syncthreads();

        const int xb = GXO + bf * GXBUF;
        const int wcol = kc * 32;
#pragma unroll
        for (int k = 0; k < 4; k++) {
            int kk = 8 * k;
            unsigned a[2][4];
#pragma unroll
            for (int mt = 0; mt < 2; mt++) {
                int orow = 32 * mw + 16 * mt;
                a[mt][0] = smu[(orow + g)     * GWS + wcol + kk + t];
                a[mt][1] = smu[(orow + g + 8) * GWS + wcol + kk + t];
                a[mt][2] = smu[(orow + g)     * GWS + wcol + kk + t + 4];
                a[mt][3] = smu[(orow + g + 8) * GWS + wcol + kk + t + 4];
            }
#pragma unroll
            for (int nt = 0; nt < 4; nt++) {
                int nn = 32 * nw + 8 * nt;
                unsigned bb[2];
                bb[0] = smu[xb + (kk + t)     * GXS + nn + g];
                bb[1] = smu[xb + (kk + t + 4) * GXS + nn + g];
                mma8(acc[0][nt], a[0], bb);
                mma8(acc[1][nt], a[1], bb);
            }
        }
        __syncthreads();
    }

#pragma unroll
    for (int mt = 0; mt < 2; mt++) {
        int orow = o0 + 32 * mw + 16 * mt;
#pragma unroll
        for (int nt = 0; nt < 4; nt++) {
            int col = n0 + 32 * nw + 8 * nt + 2 * t;
            float e0 = acc[mt][nt][0], e1 = acc[mt][nt][1];
            float e2 = acc[mt][nt][2], e3 = acc[mt][nt][3];
            if (round_out) { e0 = tf32f(e0); e1 = tf32f(e1); e2 = tf32f(e2); e3 = tf32f(e3); }
            if (orow + g < OC)
                *(float2*)&Y[((size_t)b * OC + orow + g) * N_ + col] = make_float2(e0, e1);
            if (orow + g + 8 < OC)
                *(float2*)&Y[((size_t)b * OC + orow + g + 8) * N_ + col] = make_float2(e2, e3);
        }
    }
}

// fused q/k/v: blockIdx.y selects which GEMM
__global__ __launch_bounds__(256, 2) void gemm_qkv(const float* __restrict__ x1,
                                                   const float* __restrict__ x2,
                                                   const float* __restrict__ wq,
                                                   const float* __restrict__ wk,
                                                   const float* __restrict__ wv,
                                                   float* __restrict__ q,
                                                   float* __restrict__ k,
                                                   float* __restrict__ v)
{
    int y = blockIdx.y;
    if      (y == 0) gemm_body(wq, x1, q, CR_, 0, 1);
    else if (y == 1) gemm_body(wk, x2, k, CR_, 0, 1);
    else             gemm_body(wv, x2, v, C_, (y - 2) * 64, 1);
}

__global__ __launch_bounds__(256, 2) void gemm_proj(const float* __restrict__ wp,
                                                    const float* __restrict__ ao,
                                                    float* __restrict__ yo)
{
    gemm_body(wp, ao, yo, C_, blockIdx.y * 64, 0);
}

// ============================================================================
// Attention (R6 winner): CTA = 128q x 256c per batch, 256 threads / 8 warps.
// S warp tile 32q x 32j; PV warp tile 64q x 64c (128 acc regs/thread).
// 2 barriers per 64-j tile; lsum in registers; K/V double-buffered cp.async.
// ============================================================================
#define QS_  0                       // [128][36]
#define KS_  4608                    // 2 x [32][68]
#define KBUF 2176
#define PS_  8960                    // [128][68]
#define VS_  17664                   // 2 x [256][68]
#define VBUF 17408
#define OS_  17664                   // overlay on VS: [256][132]
#define LP_  52480                   // [128][2]
#define LS_  52736                   // [128]
#define ATTN_SMEM (52864*4)

__global__ __launch_bounds__(256, 1) void attn_mma()
{
    extern __shared__ float sm[];
    unsigned* smu = (unsigned*)sm;
    unsigned sbase = (unsigned)__cvta_generic_to_shared(sm);

    const int tid = threadIdx.x, lane = tid & 31, wid = tid >> 5;
    const int g = lane >> 2, t = lane & 3;
    const int q0 = blockIdx.x * 128;
    const int b  = blockIdx.y;
    // S-phase roles: 4 q-blocks x 2 j-halves
    const int mq = wid & 3, nh = wid >> 2;
    const int qrow = 32 * mq;
    // PV-phase roles: 2 q-halves x 4 c-blocks
    const int qw = wid & 1, cw = wid >> 1;

    // ---- prologue: transpose-load Q tile -> qs[q][c] ----
#pragma unroll
    for (int s = 0; s < 4; s++) {
        int u = tid + 256 * s;               // 1024 units: 32c x 32(q/4)
        int c = u >> 5, q4 = (u & 31) * 4;
        float4 f = *(const float4*)&g_q[((size_t)b * CR_ + c) * N_ + q0 + q4];
        sm[QS_ + (q4 + 0) * 36 + c] = f.x;
        sm[QS_ + (q4 + 1) * 36 + c] = f.y;
        sm[QS_ + (q4 + 2) * 36 + c] = f.z;
        sm[QS_ + (q4 + 3) * 36 + c] = f.w;
    }

    auto loadKV = [&](int jt, int bf) {
        int j0 = jt * 64;
#pragma unroll
        for (int s = 0; s < 2; s++) {        // K: 512 float4 units
            int u = tid + 256 * s;
            int c = u >> 4, j4 = (u & 15) * 4;
            cp16(sbase + (KS_ + bf * KBUF + c * 68 + j4) * 4,
                 &g_k[((size_t)b * CR_ + c) * N_ + j0 + j4]);
        }
#pragma unroll
        for (int s = 0; s < 16; s++) {       // V: 4096 float4 units
            int u = tid + 256 * s;
            int c = u >> 4, j4 = (u & 15) * 4;
            cp16(sbase + (VS_ + bf * VBUF + c * 68 + j4) * 4,
                 &g_v[((size_t)b * C_ + c) * N_ + j0 + j4]);
        }
    };

    float oacc[4][8][4];
#pragma unroll
    for (int i = 0; i < 4; i++)
#pragma unroll
        for (int j = 0; j < 8; j++)
#pragma unroll
            for (int e = 0; e < 4; e++) oacc[i][j][e] = 0.f;

    float lreg[2][2] = {{0.f, 0.f}, {0.f, 0.f}};   // [m-tile][row-half] running denominators

    loadKV(0, 0); cpcommit();

    for (int jt = 0; jt < N_ / 64; jt++) {
        const int bf = jt & 1;
        cpwait<0>();
        __syncthreads();   // KV(bf) visible; PV(jt-1)/S(jt-1) done with buffers bf^1 and PS

        if (jt + 1 < N_ / 64) { loadKV(jt + 1, bf ^ 1); cpcommit(); }

        // ---------------- S = Q^T K, p = exp2(S*SEXP) -> PS ----------------
        {
            const int kb = KS_ + bf * KBUF;
            float sacc[2][4][4];
#pragma unroll
            for (int mt = 0; mt < 2; mt++)
#pragma unroll
                for (int nt = 0; nt < 4; nt++)
#pragma unroll
                    for (int e = 0; e < 4; e++) sacc[mt][nt][e] = 0.f;

#pragma unroll
            for (int k = 0; k < 4; k++) {
                int kk = 8 * k;
                unsigned a[2][4];
#pragma unroll
                for (int mt = 0; mt < 2; mt++) {
                    int r = qrow + 16 * mt;
                    a[mt][0] = smu[QS_ + (r + g)     * 36 + kk + t];
                    a[mt][1] = smu[QS_ + (r + g + 8) * 36 + kk + t];
                    a[mt][2] = smu[QS_ + (r + g)     * 36 + kk + t + 4];
                    a[mt][3] = smu[QS_ + (r + g + 8) * 36 + kk + t + 4];
                }
#pragma unroll
                for (int nt = 0; nt < 4; nt++) {
                    int jj = 32 * nh + 8 * nt;
                    unsigned bb[2];
                    bb[0] = smu[kb + (kk + t)     * 68 + jj + g];
                    bb[1] = smu[kb + (kk + t + 4) * 68 + jj + g];
                    mma8(sacc[0][nt], a[0], bb);
                    mma8(sacc[1][nt], a[1], bb);
                }
            }
#pragma unroll
            for (int mt = 0; mt < 2; mt++) {
                int r = qrow + 16 * mt;
#pragma unroll
                for (int nt = 0; nt < 4; nt++) {
                    int jj = 32 * nh + 8 * nt + 2 * t;
                    float e0 = tf32f(ex2(sacc[mt][nt][0] * SEXP_));
                    float e1 = tf32f(ex2(sacc[mt][nt][1] * SEXP_));
                    float e2 = tf32f(ex2(sacc[mt][nt][2] * SEXP_));
                    float e3 = tf32f(ex2(sacc[mt][nt][3] * SEXP_));
                    lreg[mt][0] += e0 + e1;
                    lreg[mt][1] += e2 + e3;
                    *(float2*)&sm[PS_ + (r + g)     * 68 + jj] = make_float2(e0, e1);
                    *(float2*)&sm[PS_ + (r + g + 8) * 68 + jj] = make_float2(e2, e3);
                }
            }
        }
        __syncthreads();   // PS ready

        // ---------------- O += P V^T ----------------
        {
            const int vb = VS_ + bf * VBUF;
#pragma unroll
            for (int k = 0; k < 8; k++) {
                int kk = 8 * k;
                unsigned a[4][4];
#pragma unroll
                for (int mt = 0; mt < 4; mt++) {
                    int r = 64 * qw + 16 * mt;
                    a[mt][0] = smu[PS_ + (r + g)     * 68 + kk + t];
                    a[mt][1] = smu[PS_ + (r + g + 8) * 68 + kk + t];
                    a[mt][2] = smu[PS_ + (r + g)     * 68 + kk + t + 4];
                    a[mt][3] = smu[PS_ + (r + g + 8) * 68 + kk + t + 4];
                }
#pragma unroll
                for (int nt = 0; nt < 8; nt++) {
                    int cc = 64 * cw + 8 * nt;
                    unsigned bb[2];
                    bb[0] = smu[vb + (cc + g) * 68 + kk + t];
                    bb[1] = smu[vb + (cc + g) * 68 + kk + t + 4];
#pragma unroll
                    for (int mt = 0; mt < 4; mt++) mma8(oacc[mt][nt], a[mt], bb);
                }
            }
        }
        // next iteration's top barrier protects PS and V(bf)
    }

    // ---- denominators: reduce register partials ----
    {
        float r0 = lreg[0][0], r1 = lreg[0][1], r2 = lreg[1][0], r3 = lreg[1][1];
        r0 += __shfl_xor_sync(0xffffffffu, r0, 1); r0 += __shfl_xor_sync(0xffffffffu, r0, 2);
        r1 += __shfl_xor_sync(0xffffffffu, r1, 1); r1 += __shfl_xor_sync(0xffffffffu, r1, 2);
        r2 += __shfl_xor_sync(0xffffffffu, r2, 1); r2 += __shfl_xor_sync(0xffffffffu, r2, 2);
        r3 += __shfl_xor_sync(0xffffffffu, r3, 1); r3 += __shfl_xor_sync(0xffffffffu, r3, 2);
        if (t == 0) {
            sm[LP_ + (qrow + g)      * 2 + nh] = r0;
            sm[LP_ + (qrow + g + 8)  * 2 + nh] = r1;
            sm[LP_ + (qrow + g + 16) * 2 + nh] = r2;
            sm[LP_ + (qrow + g + 24) * 2 + nh] = r3;
        }
    }
    __syncthreads();
    if (tid < 128) sm[LS_ + tid] = 1.f / (sm[LP_ + 2 * tid] + sm[LP_ + 2 * tid + 1]);
    __syncthreads();

    // ---- scale + transpose through smem (overlay on VS), coalesced store ----
#pragma unroll
    for (int mt = 0; mt < 4; mt++) {
        int row0 = 64 * qw + 16 * mt + g;
        float inv0 = sm[LS_ + row0];
        float inv1 = sm[LS_ + row0 + 8];
#pragma unroll
        for (int nt = 0; nt < 8; nt++) {
            int cc = 64 * cw + 8 * nt + 2 * t;
            sm[OS_ + cc       * 132 + row0]     = tf32f(oacc[mt][nt][0] * inv0);
            sm[OS_ + (cc + 1) * 132 + row0]     = tf32f(oacc[mt][nt][1] * inv0);
            sm[OS_ + cc       * 132 + row0 + 8] = tf32f(oacc[mt][nt][2] * inv1);
            sm[OS_ + (cc + 1) * 132 + row0 + 8] = tf32f(oacc[mt][nt][3] * inv1);
        }
    }
    __syncthreads();
#pragma unroll
    for (int s = 0; s < 32; s++) {
        int u = tid + 256 * s;               // 8192 float4 units: 256c x 32(q/4)
        int c = u >> 5, q4 = (u & 31) * 4;
        float4 f = *(const float4*)&sm[OS_ + c * 132 + q4];
        *(float4*)&g_ao[((size_t)b * C_ + c) * N_ + q0 + q4] = f;
    }
}

// ---------------- instance norm + residual ----------------
__global__ __launch_bounds__(256) void norm_kernel(const float* __restrict__ x1,
                                                   float* __restrict__ out)
{
    int row = blockIdx.x;
    const float* yr = g_y + (size_t)row * N_;
    const float* xr = x1  + (size_t)row * N_;
    float*       orow = out + (size_t)row * N_;
    int tid = threadIdx.x;

    float4 v[4];
    float s = 0.f, ss = 0.f;
#pragma unroll
    for (int k = 0; k < 4; k++) {
        v[k] = *(const float4*)&yr[(tid + 256 * k) * 4];
        s  += v[k].x + v[k].y + v[k].z + v[k].w;
        ss += v[k].x * v[k].x + v[k].y * v[k].y + v[k].z * v[k].z + v[k].w * v[k].w;
    }
#pragma unroll
    for (int o = 16; o; o >>= 1) {
        s  += __shfl_xor_sync(0xffffffffu, s,  o);
        ss += __shfl_xor_sync(0xffffffffu, ss, o);
    }
    __shared__ float rs[8], rss[8];
    __shared__ float stats[2];
    if ((tid & 31) == 0) { rs[tid >> 5] = s; rss[tid >> 5] = ss; }
    __syncthreads();
    if (tid < 32) {
        float a  = (tid < 8) ? rs[tid]  : 0.f;
        float b2 = (tid < 8) ? rss[tid] : 0.f;
#pragma unroll
        for (int o = 4; o; o >>= 1) {
            a  += __shfl_xor_sync(0xffffffffu, a,  o);
            b2 += __shfl_xor_sync(0xffffffffu, b2, o);
        }
        if (tid == 0) {
            float mean = a * (1.f / N_);
            float var  = b2 * (1.f / N_) - mean * mean;
            stats[0] = mean;
            stats[1] = rsqrtf(var + EPS_);
        }
    }
    __syncthreads();
    float mean = stats[0], inv = stats[1];
#pragma unroll
    for (int k = 0; k < 4; k++) {
        float4 x4 = *(const float4*)&xr[(tid + 256 * k) * 4];
        float4 o4;
        o4.x = (v[k].x - mean) * inv + x4.x;
        o4.y = (v[k].y - mean) * inv + x4.y;
        o4.z = (v[k].z - mean) * inv + x4.z;
        o4.w = (v[k].w - mean) * inv + x4.w;
        *(float4*)&orow[(tid + 256 * k) * 4] = o4;
    }
}

// ---------------- launcher ----------------
extern "C" void kernel_launch(void* const* d_in, const int* in_sizes, int n_in,
                              void* d_out, int out_size)
{
    (void)in_sizes; (void)n_in; (void)out_size;
    const float* x1 = (const float*)d_in[0];
    const float* x2 = (const float*)d_in[1];
    const float* wq = (const float*)d_in[2];
    const float* wk = (const float*)d_in[3];
    const float* wv = (const float*)d_in[4];
    const float* wp = (const float*)d_in[5];
    float* out = (float*)d_out;

    void *qp, *kp, *vp, *aop, *yp;
    cudaGetSymbolAddress(&qp,  g_q);
    cudaGetSymbolAddress(&kp,  g_k);
    cudaGetSymbolAddress(&vp,  g_v);
    cudaGetSymbolAddress(&aop, g_ao);
    cudaGetSymbolAddress(&yp,  g_y);

    cudaFuncSetAttribute(gemm_qkv,  cudaFuncAttributeMaxDynamicSharedMemorySize, GEMM_SMEM);
    cudaFuncSetAttribute(gemm_proj, cudaFuncAttributeMaxDynamicSharedMemorySize, GEMM_SMEM);
    cudaFuncSetAttribute(attn_mma,  cudaFuncAttributeMaxDynamicSharedMemorySize, ATTN_SMEM);

    gemm_qkv<<<dim3(N_/128, 6, B_), 256, GEMM_SMEM>>>(x1, x2, wq, wk, wv,
                                                      (float*)qp, (float*)kp, (float*)vp);
    attn_mma<<<dim3(N_/128, B_), 256, ATTN_SMEM>>>();
    gemm_proj<<<dim3(N_/128, C_/64, B_), 256, GEMM_SMEM>>>(wp, (const float*)aop, (float*)yp);
    norm_kernel<<<B_*C_, 256>>>(x1, out);
}

// round 11
// speedup vs baseline: 1.2477x; 1.0239x over previous
#include <cuda_runtime.h>

#define B_   4
#define C_   256
#define CR_  32
#define N_   4096
#define EPS_ 1e-5f
#define SEXP_ 0.25503486f   // (1/sqrt(32)) * log2(e)

// ---------------- scratch (device globals; no allocations) ----------------
__device__ float g_q [B_*CR_*N_];
__device__ float g_k [B_*CR_*N_];
__device__ float g_v [B_*C_*N_];
__device__ float g_ao[B_*C_*N_];
__device__ float g_y [B_*C_*N_];

// ---------------- helpers ----------------
__device__ __forceinline__ unsigned tf32r(float x){
    unsigned r; asm("cvt.rna.tf32.f32 %0, %1;" : "=r"(r) : "f"(x)); return r;
}
__device__ __forceinline__ float tf32f(float x){ return __uint_as_float(tf32r(x)); }
__device__ __forceinline__ float ex2(float x){
    float r; asm("ex2.approx.f32 %0, %1;" : "=f"(r) : "f"(x)); return r;
}
__device__ __forceinline__ void mma8(float* d, const unsigned* a, const unsigned* b){
    asm volatile("mma.sync.aligned.m16n8k8.row.col.f32.tf32.tf32.f32 "
        "{%0,%1,%2,%3},{%4,%5,%6,%7},{%8,%9},{%0,%1,%2,%3};"
        : "+f"(d[0]), "+f"(d[1]), "+f"(d[2]), "+f"(d[3])
        : "r"(a[0]), "r"(a[1]), "r"(a[2]), "r"(a[3]), "r"(b[0]), "r"(b[1]));
}
__device__ __forceinline__ void cp16(unsigned daddr, const void* src){
    asm volatile("cp.async.cg.shared.global [%0], [%1], 16;" :: "r"(daddr), "l"(src));
}
__device__ __forceinline__ void cpcommit(){ asm volatile("cp.async.commit_group;"); }
template<int n> __device__ __forceinline__ void cpwait(){
    asm volatile("cp.async.wait_group %0;" :: "n"(n));
}

// ============================================================================
// Channel GEMM body: Y[b,o(+o0),n] = sum_c W[o0+o,c] * X[b,c,n]   (K = 256)
// ============================================================================
#define GWS 260
#define GXS 132
#define GXO (64*GWS)
#define GXBUF (32*GXS)
#define GEMM_SMEM ((GXO + 2*GXBUF)*4)

__device__ __forceinline__ void gemm_body(const float* __restrict__ W,
                                          const float* __restrict__ X,
                                          float* __restrict__ Y,
                                          int OC, int o0, int round_out)
{
    extern __shared__ float sm[];
    unsigned* smu = (unsigned*)sm;
    unsigned sbase = (unsigned)__cvta_generic_to_shared(sm);

    const int tid = threadIdx.x, lane = tid & 31, wid = tid >> 5;
    const int g = lane >> 2, t = lane & 3;
    const int mw = wid >> 2, nw = wid & 3;
    const int n0 = blockIdx.x * 128;
    const int b  = blockIdx.z;
    const float* Xb = X + (size_t)b * C_ * N_;

#pragma unroll
    for (int s = 0; s < 16; s++) {
        int u = tid + 256 * s;
        int o = u >> 6, c4 = (u & 63) * 4;
        float4 w4 = make_float4(0.f, 0.f, 0.f, 0.f);
        if (o0 + o < OC) w4 = *(const float4*)&W[(size_t)(o0 + o) * C_ + c4];
        w4.x = tf32f(w4.x); w4.y = tf32f(w4.y); w4.z = tf32f(w4.z); w4.w = tf32f(w4.w);
        *(float4*)&sm[o * GWS + c4] = w4;
    }

    auto loadX = [&](int kc, int bf) {
#pragma unroll
        for (int s = 0; s < 4; s++) {
            int u = tid + 256 * s;
            int c = u >> 5, n4 = (u & 31) * 4;
            cp16(sbase + (GXO + bf * GXBUF + c * GXS + n4) * 4,
                 &Xb[(size_t)(kc * 32 + c) * N_ + n0 + n4]);
        }
    };

    float acc[2][4][4];
#pragma unroll
    for (int i = 0; i < 2; i++)
#pragma unroll
        for (int j = 0; j < 4; j++)
#pragma unroll
            for (int e = 0; e < 4; e++) acc[i][j][e] = 0.f;

    loadX(0, 0); cpcommit();

    for (int kc = 0; kc < 8; kc++) {
        int bf = kc & 1;
        if (kc < 7) { loadX(kc + 1, bf ^ 1); cpcommit(); cpwait<1>(); }
        else        { cpwait<0>(); }
        __syncthreads();

        const int xb = GXO + bf * GXBUF;
        const int wcol = kc * 32;
#pragma unroll
        for (int k = 0; k < 4; k++) {
            int kk = 8 * k;
            unsigned a[2][4];
#pragma unroll
            for (int mt = 0; mt < 2; mt++) {
                int orow = 32 * mw + 16 * mt;
                a[mt][0] = smu[(orow + g)     * GWS + wcol + kk + t];
                a[mt][1] = smu[(orow + g + 8) * GWS + wcol + kk + t];
                a[mt][2] = smu[(orow + g)     * GWS + wcol + kk + t + 4];
                a[mt][3] = smu[(orow + g + 8) * GWS + wcol + kk + t + 4];
            }
#pragma unroll
            for (int nt = 0; nt < 4; nt++) {
                int nn = 32 * nw + 8 * nt;
                unsigned bb[2];
                bb[0] = smu[xb + (kk + t)     * GXS + nn + g];
                bb[1] = smu[xb + (kk + t + 4) * GXS + nn + g];
                mma8(acc[0][nt], a[0], bb);
                mma8(acc[1][nt], a[1], bb);
            }
        }
        __syncthreads();
    }

#pragma unroll
    for (int mt = 0; mt < 2; mt++) {
        int orow = o0 + 32 * mw + 16 * mt;
#pragma unroll
        for (int nt = 0; nt < 4; nt++) {
            int col = n0 + 32 * nw + 8 * nt + 2 * t;
            float e0 = acc[mt][nt][0], e1 = acc[mt][nt][1];
            float e2 = acc[mt][nt][2], e3 = acc[mt][nt][3];
            if (round_out) { e0 = tf32f(e0); e1 = tf32f(e1); e2 = tf32f(e2); e3 = tf32f(e3); }
            if (orow + g < OC)
                *(float2*)&Y[((size_t)b * OC + orow + g) * N_ + col] = make_float2(e0, e1);
            if (orow + g + 8 < OC)
                *(float2*)&Y[((size_t)b * OC + orow + g + 8) * N_ + col] = make_float2(e2, e3);
        }
    }
}

// fused q/k/v: blockIdx.y selects which GEMM
__global__ __launch_bounds__(256, 2) void gemm_qkv(const float* __restrict__ x1,
                                                   const float* __restrict__ x2,
                                                   const float* __restrict__ wq,
                                                   const float* __restrict__ wk,
                                                   const float* __restrict__ wv,
                                                   float* __restrict__ q,
                                                   float* __restrict__ k,
                                                   float* __restrict__ v)
{
    int y = blockIdx.y;
    if      (y == 0) gemm_body(wq, x1, q, CR_, 0, 1);
    else if (y == 1) gemm_body(wk, x2, k, CR_, 0, 1);
    else             gemm_body(wv, x2, v, C_, (y - 2) * 64, 1);
}

__global__ __launch_bounds__(256, 2) void gemm_proj(const float* __restrict__ wp,
                                                    const float* __restrict__ ao,
                                                    float* __restrict__ yo)
{
    gemm_body(wp, ao, yo, C_, blockIdx.y * 64, 0);
}

// ============================================================================
// Attention: CTA = 128q x 256c per batch, 256 threads / 8 warps.
// ONE barrier per 64-j iteration: compute S(jt+1) then PV(jt) back-to-back
// (PS double-buffered, Q fragments in registers, K prefetch distance 2).
// ============================================================================
#define KS_  0                        // 2 x [32][68] = 4352
#define KBUF 2176
#define PS_  4352                     // 2 x [128][68] = 17408
#define PBUF 8704
#define VS_  21760                    // 2 x [256][68] = 34816
#define VBUF 17408
#define OS_  21760                    // epilogue overlay [256][132] = 33792 (inside VS)
#define LP_  56576                    // [128][2]
#define LS_  56832                    // [128]
#define ATTN_SMEM (56960*4)           // 227,840 B

__global__ __launch_bounds__(256, 1) void attn_mma()
{
    extern __shared__ float sm[];
    unsigned* smu = (unsigned*)sm;
    unsigned sbase = (unsigned)__cvta_generic_to_shared(sm);

    const int tid = threadIdx.x, lane = tid & 31, wid = tid >> 5;
    const int g = lane >> 2, t = lane & 3;
    const int q0 = blockIdx.x * 128;
    const int b  = blockIdx.y;
    // S-phase roles: 4 q-blocks x 2 j-halves
    const int mq = wid & 3, nh = wid >> 2;
    const int qrow = 32 * mq;
    // PV-phase roles: 2 q-halves x 4 c-blocks
    const int qw = wid & 1, cw = wid >> 1;

    auto loadK = [&](int jt, int bf) {
        int j0 = jt * 64;
#pragma unroll
        for (int s = 0; s < 2; s++) {        // 512 float4 units
            int u = tid + 256 * s;
            int c = u >> 4, j4 = (u & 15) * 4;
            cp16(sbase + (KS_ + bf * KBUF + c * 68 + j4) * 4,
                 &g_k[((size_t)b * CR_ + c) * N_ + j0 + j4]);
        }
    };
    auto loadV = [&](int jt, int bf) {
        int j0 = jt * 64;
#pragma unroll
        for (int s = 0; s < 16; s++) {       // 4096 float4 units
            int u = tid + 256 * s;
            int c = u >> 4, j4 = (u & 15) * 4;
            cp16(sbase + (VS_ + bf * VBUF + c * 68 + j4) * 4,
                 &g_v[((size_t)b * C_ + c) * N_ + j0 + j4]);
        }
    };

    // ---- prologue: issue K(0), V(0), K(1); load Q fragments into registers ----
    loadK(0, 0); loadV(0, 0); loadK(1, 1); cpcommit();

    unsigned qf[4][2][4];                    // [k-step][m-tile][frag] — tf32 already
    {
        const float* qb = g_q + (size_t)b * CR_ * N_;
#pragma unroll
        for (int k = 0; k < 4; k++) {
#pragma unroll
            for (int mt = 0; mt < 2; mt++) {
                int qq = q0 + qrow + 16 * mt + g;
                qf[k][mt][0] = __float_as_uint(qb[(size_t)(8 * k + t)     * N_ + qq]);
                qf[k][mt][1] = __float_as_uint(qb[(size_t)(8 * k + t)     * N_ + qq + 8]);
                qf[k][mt][2] = __float_as_uint(qb[(size_t)(8 * k + t + 4) * N_ + qq]);
                qf[k][mt][3] = __float_as_uint(qb[(size_t)(8 * k + t + 4) * N_ + qq + 8]);
            }
        }
    }

    float oacc[4][8][4];
#pragma unroll
    for (int i = 0; i < 4; i++)
#pragma unroll
        for (int j = 0; j < 8; j++)
#pragma unroll
            for (int e = 0; e < 4; e++) oacc[i][j][e] = 0.f;

    float lreg[2][2] = {{0.f, 0.f}, {0.f, 0.f}};

    // ---- S-tile compute: S = Q^T K -> exp -> PS[pso], denominators ----
    auto computeS = [&](int kb, int pso) {
        float sacc[2][4][4];
#pragma unroll
        for (int mt = 0; mt < 2; mt++)
#pragma unroll
            for (int nt = 0; nt < 4; nt++)
#pragma unroll
                for (int e = 0; e < 4; e++) sacc[mt][nt][e] = 0.f;
#pragma unroll
        for (int k = 0; k < 4; k++) {
            int kk = 8 * k;
#pragma unroll
            for (int nt = 0; nt < 4; nt++) {
                int jj = 32 * nh + 8 * nt;
                unsigned bb[2];
                bb[0] = smu[kb + (kk + t)     * 68 + jj + g];
                bb[1] = smu[kb + (kk + t + 4) * 68 + jj + g];
                mma8(sacc[0][nt], qf[k][0], bb);
                mma8(sacc[1][nt], qf[k][1], bb);
            }
        }
#pragma unroll
        for (int mt = 0; mt < 2; mt++) {
            int r = qrow + 16 * mt;
#pragma unroll
            for (int nt = 0; nt < 4; nt++) {
                int jj = 32 * nh + 8 * nt + 2 * t;
                float e0 = tf32f(ex2(sacc[mt][nt][0] * SEXP_));
                float e1 = tf32f(ex2(sacc[mt][nt][1] * SEXP_));
                float e2 = tf32f(ex2(sacc[mt][nt][2] * SEXP_));
                float e3 = tf32f(ex2(sacc[mt][nt][3] * SEXP_));
                lreg[mt][0] += e0 + e1;
                lreg[mt][1] += e2 + e3;
                *(float2*)&sm[pso + (r + g)     * 68 + jj] = make_float2(e0, e1);
                *(float2*)&sm[pso + (r + g + 8) * 68 + jj] = make_float2(e2, e3);
            }
        }
    };

    // ---- PV compute: O += P V^T ----
    auto computePV = [&](int pso, int vb) {
#pragma unroll
        for (int k = 0; k < 8; k++) {
            int kk = 8 * k;
            unsigned a[4][4];
#pragma unroll
            for (int mt = 0; mt < 4; mt++) {
                int r = 64 * qw + 16 * mt;
                a[mt][0] = smu[pso + (r + g)     * 68 + kk + t];
                a[mt][1] = smu[pso + (r + g + 8) * 68 + kk + t];
                a[mt][2] = smu[pso + (r + g)     * 68 + kk + t + 4];
                a[mt][3] = smu[pso + (r + g + 8) * 68 + kk + t + 4];
            }
#pragma unroll
            for (int nt = 0; nt < 8; nt++) {
                int cc = 64 * cw + 8 * nt;
                unsigned bb[2];
                bb[0] = smu[vb + (cc + g) * 68 + kk + t];
                bb[1] = smu[vb + (cc + g) * 68 + kk + t + 4];
#pragma unroll
                for (int mt = 0; mt < 4; mt++) mma8(oacc[mt][nt], a[mt], bb);
            }
        }
    };

    // ---- prologue S(0) ----
    cpwait<0>();
    __syncthreads();
    computeS(KS_ + 0, PS_ + 0);

    // ---- main loop: one barrier per iteration ----
    for (int jt = 0; jt < N_ / 64; jt++) {
        const int p = jt & 1;
        cpwait<0>();
        __syncthreads();   // ready: K(jt+1), V(jt), PS[p]; PS[p^1]/K[jt&1]/V[(jt+1)&1] free

        if (jt + 2 < N_ / 64) loadK(jt + 2, jt & 1);
        if (jt + 1 < N_ / 64) loadV(jt + 1, (jt + 1) & 1);
        cpcommit();

        if (jt + 1 < N_ / 64) computeS(KS_ + ((jt + 1) & 1) * KBUF, PS_ + (p ^ 1) * PBUF);
        computePV(PS_ + p * PBUF, VS_ + p * VBUF);
    }

    // ---- denominators: reduce register partials ----
    {
        float r0 = lreg[0][0], r1 = lreg[0][1], r2 = lreg[1][0], r3 = lreg[1][1];
        r0 += __shfl_xor_sync(0xffffffffu, r0, 1); r0 += __shfl_xor_sync(0xffffffffu, r0, 2);
        r1 += __shfl_xor_sync(0xffffffffu, r1, 1); r1 += __shfl_xor_sync(0xffffffffu, r1, 2);
        r2 += __shfl_xor_sync(0xffffffffu, r2, 1); r2 += __shfl_xor_sync(0xffffffffu, r2, 2);
        r3 += __shfl_xor_sync(0xffffffffu, r3, 1); r3 += __shfl_xor_sync(0xffffffffu, r3, 2);
        if (t == 0) {
            sm[LP_ + (qrow + g)      * 2 + nh] = r0;
            sm[LP_ + (qrow + g + 8)  * 2 + nh] = r1;
            sm[LP_ + (qrow + g + 16) * 2 + nh] = r2;
            sm[LP_ + (qrow + g + 24) * 2 + nh] = r3;
        }
    }
    __syncthreads();
    if (tid < 128) sm[LS_ + tid] = 1.f / (sm[LP_ + 2 * tid] + sm[LP_ + 2 * tid + 1]);
    __syncthreads();

    // ---- scale + transpose through smem overlay, coalesced store ----
#pragma unroll
    for (int mt = 0; mt < 4; mt++) {
        int row0 = 64 * qw + 16 * mt + g;
        float inv0 = sm[LS_ + row0];
        float inv1 = sm[LS_ + row0 + 8];
#pragma unroll
        for (int nt = 0; nt < 8; nt++) {
            int cc = 64 * cw + 8 * nt + 2 * t;
            sm[OS_ + cc       * 132 + row0]     = tf32f(oacc[mt][nt][0] * inv0);
            sm[OS_ + (cc + 1) * 132 + row0]     = tf32f(oacc[mt][nt][1] * inv0);
            sm[OS_ + cc       * 132 + row0 + 8] = tf32f(oacc[mt][nt][2] * inv1);
            sm[OS_ + (cc + 1) * 132 + row0 + 8] = tf32f(oacc[mt][nt][3] * inv1);
        }
    }
    __syncthreads();
#pragma unroll
    for (int s = 0; s < 32; s++) {
        int u = tid + 256 * s;               // 8192 float4 units: 256c x 32(q/4)
        int c = u >> 5, q4 = (u & 31) * 4;
        float4 f = *(const float4*)&sm[OS_ + c * 132 + q4];
        *(float4*)&g_ao[((size_t)b * C_ + c) * N_ + q0 + q4] = f;
    }
}

// ---------------- instance norm + residual ----------------
__global__ __launch_bounds__(256) void norm_kernel(const float* __restrict__ x1,
                                                   float* __restrict__ out)
{
    int row = blockIdx.x;
    const float* yr = g_y + (size_t)row * N_;
    const float* xr = x1  + (size_t)row * N_;
    float*       orow = out + (size_t)row * N_;
    int tid = threadIdx.x;

    float4 v[4];
    float s = 0.f, ss = 0.f;
#pragma unroll
    for (int k = 0; k < 4; k++) {
        v[k] = *(const float4*)&yr[(tid + 256 * k) * 4];
        s  += v[k].x + v[k].y + v[k].z + v[k].w;
        ss += v[k].x * v[k].x + v[k].y * v[k].y + v[k].z * v[k].z + v[k].w * v[k].w;
    }
#pragma unroll
    for (int o = 16; o; o >>= 1) {
        s  += __shfl_xor_sync(0xffffffffu, s,  o);
        ss += __shfl_xor_sync(0xffffffffu, ss, o);
    }
    __shared__ float rs[8], rss[8];
    __shared__ float stats[2];
    if ((tid & 31) == 0) { rs[tid >> 5] = s; rss[tid >> 5] = ss; }
    __syncthreads();
    if (tid < 32) {
        float a  = (tid < 8) ? rs[tid]  : 0.f;
        float b2 = (tid < 8) ? rss[tid] : 0.f;
#pragma unroll
        for (int o = 4; o; o >>= 1) {
            a  += __shfl_xor_sync(0xffffffffu, a,  o);
            b2 += __shfl_xor_sync(0xffffffffu, b2, o);
        }
        if (tid == 0) {
            float mean = a * (1.f / N_);
            float var  = b2 * (1.f / N_) - mean * mean;
            stats[0] = mean;
            stats[1] = rsqrtf(var + EPS_);
        }
    }
    __syncthreads();
    float mean = stats[0], inv = stats[1];
#pragma unroll
    for (int k = 0; k < 4; k++) {
        float4 x4 = *(const float4*)&xr[(tid + 256 * k) * 4];
        float4 o4;
        o4.x = (v[k].x - mean) * inv + x4.x;
        o4.y = (v[k].y - mean) * inv + x4.y;
        o4.z = (v[k].z - mean) * inv + x4.z;
        o4.w = (v[k].w - mean) * inv + x4.w;
        *(float4*)&orow[(tid + 256 * k) * 4] = o4;
    }
}

// ---------------- launcher ----------------
extern "C" void kernel_launch(void* const* d_in, const int* in_sizes, int n_in,
                              void* d_out, int out_size)
{
    (void)in_sizes; (void)n_in; (void)out_size;
    const float* x1 = (const float*)d_in[0];
    const float* x2 = (const float*)d_in[1];
    const float* wq = (const float*)d_in[2];
    const float* wk = (const float*)d_in[3];
    const float* wv = (const float*)d_in[4];
    const float* wp = (const float*)d_in[5];
    float* out = (float*)d_out;

    void *qp, *kp, *vp, *aop, *yp;
    cudaGetSymbolAddress(&qp,  g_q);
    cudaGetSymbolAddress(&kp,  g_k);
    cudaGetSymbolAddress(&vp,  g_v);
    cudaGetSymbolAddress(&aop, g_ao);
    cudaGetSymbolAddress(&yp,  g_y);

    cudaFuncSetAttribute(gemm_qkv,  cudaFuncAttributeMaxDynamicSharedMemorySize, GEMM_SMEM);
    cudaFuncSetAttribute(gemm_proj, cudaFuncAttributeMaxDynamicSharedMemorySize, GEMM_SMEM);
    cudaFuncSetAttribute(attn_mma,  cudaFuncAttributeMaxDynamicSharedMemorySize, ATTN_SMEM);

    gemm_qkv<<<dim3(N_/128, 6, B_), 256, GEMM_SMEM>>>(x1, x2, wq, wk, wv,
                                                      (float*)qp, (float*)kp, (float*)vp);
    attn_mma<<<dim3(N_/128, B_), 256, ATTN_SMEM>>>();
    gemm_proj<<<dim3(N_/128, C_/64, B_), 256, GEMM_SMEM>>>(wp, (const float*)aop, (float*)yp);
    norm_kernel<<<B_*C_, 256>>>(x1, out);
}